// round 7
// baseline (speedup 1.0000x reference)
#include <cuda_runtime.h>
#include <cstddef>

// Two-layer LSTM recurrence, persistent kernel, j-paired f32x2 GEMV.
// R7: BT=8 / G=4 batch groups -> 25% less SMEM crossbar traffic than R6
// (lane-bytes per j: 1600*G + 12800). Conflict-free everywhere:
//   - W rows at stride 404 (u-quads distinct)
//   - h rows [50][76], batch group g at word g*20 (+0,4,8,12 loads ->
//     bank quads {0,20,8,28}+4k, distinct in every LDS.128 phase)
//   - c1 rows at stride 36 (write quads distinct across u within a warp)
//
// 128 blocks x 432 threads:
//   tid <  400 : layer-1. unit u = tid>>2, batch group t4 = tid&3, BT=8.
//   tid >= 400 : layer-2 (one warp; lane = batch elem), one step behind.

#define CELL     100
#define NJ2      50       // CELL/2 j-pairs
#define NB       32       // batch per block
#define BT       8        // batch per layer-1 thread
#define THREADS  432
#define L2BASE   400
#define WSTRIDE  404      // 404 mod 32 = 20 -> consecutive u hit distinct quads
#define HSTRIDE  76       // hpair row stride
#define CSTRIDE  36       // c1sh row stride

#define FMA2(acc, a, b) asm("fma.rn.f32x2 %0,%1,%2,%0;" : "+l"(acc) : "l"(a), "l"(b))
#define UNPK2(lo, hi, s) asm("mov.b64 {%0,%1},%2;" : "=f"(lo), "=f"(hi) : "l"(s))

__device__ __forceinline__ float sigm(float x) {
    return 1.0f / (1.0f + __expf(-x));
}
__device__ __forceinline__ float tanh_f(float x) {
    float e = __expf(2.0f * x);
    return 1.0f - 2.0f / (e + 1.0f);
}

__global__ void __launch_bounds__(THREADS, 1)
tsrnn_kernel(const float* __restrict__ input,
             const float* __restrict__ W_ih1, const float* __restrict__ W_hh1,
             const float* __restrict__ b_ih1, const float* __restrict__ b_hh1,
             const float* __restrict__ W_ih2, const float* __restrict__ W_hh2,
             const float* __restrict__ b_ih2, const float* __restrict__ b_hh2,
             float* __restrict__ out, int T, int FUT, int Btot)
{
    extern __shared__ float sm[];
    float* Wint  = sm;                      // [100][404]: u*404 + j2*8 + k*2 + p
    float* hpair = Wint  + CELL * WSTRIDE;  // [50][76]: group t4 at word t4*20
    float* c1sh  = hpair + NJ2 * HSTRIDE;   // [100][36]
    float* w2i   = c1sh  + CELL * CSTRIDE;  // [100][4] gate-interleaved W_ih2
    float* c2sh  = w2i   + CELL * 4;        // [32]

    const int tid    = threadIdx.x;
    const int bglob0 = blockIdx.x * NB;

    const bool l1 = (tid < L2BASE);
    const bool l2 = (tid >= L2BASE) && (tid < L2BASE + NB);
    const int  u  = tid >> 2;               // layer-1 unit (0..99)
    const int  t4 = tid & 3;                // batch group
    const int  b0 = t4 * BT;                // first batch elem

    // ---- stage W_hh1: j-paired, gate-major within pair ----
    for (int idx = tid; idx < 4 * CELL * CELL; idx += THREADS) {
        int uu = idx / 400, rem = idx - uu * 400;
        int j2 = rem >> 3, k = (rem >> 1) & 3, p = rem & 1;
        int j  = 2 * j2 + p;
        Wint[uu * WSTRIDE + j2 * 8 + k * 2 + p] = W_hh1[(k * CELL + uu) * CELL + j];
    }
    for (int idx = tid; idx < 4 * CELL; idx += THREADS) {
        int uu = idx >> 2, k = idx & 3;
        w2i[uu * 4 + k] = W_ih2[k * CELL + uu];
    }
    for (int idx = tid; idx < NJ2 * HSTRIDE; idx += THREADS) hpair[idx] = 0.0f;
    for (int idx = tid; idx < CELL * CSTRIDE; idx += THREADS) c1sh[idx] = 0.0f;
    if (tid < NB) c2sh[tid] = 0.0f;

    // layer-1 per-thread constants
    float wih[4], bsum[4];
    if (l1) {
        #pragma unroll
        for (int k = 0; k < 4; k++) {
            int g = k * CELL + u;
            wih[k]  = W_ih1[g];
            bsum[k] = b_ih1[g] + b_hh1[g];
        }
    }
    // layer-2 per-lane constants + state
    const int bl2 = tid - L2BASE;            // lane = batch elem (0..31)
    float whh2[4], b2c[4];
    float h2 = 0.0f, c2 = 0.0f;
    if (l2) {
        #pragma unroll
        for (int k = 0; k < 4; k++) {
            whh2[k] = W_hh2[k];
            b2c[k]  = b_ih2[k] + b_hh2[k];
        }
    }

    float c1r[BT];
    #pragma unroll
    for (int bb = 0; bb < BT; bb++) c1r[bb] = 0.0f;

    const float* wp = Wint  + u * WSTRIDE;
    const float* hp = hpair + t4 * 20;       // 16 floats = pairs for b0..b0+7

    // h write base (j-paired layout: unit u -> row u>>1, slot u&1)
    float* hw = hpair + (u >> 1) * HSTRIDE + t4 * 20 + (u & 1);

    __syncthreads();

    const int TOT = T + FUT;
    for (int t = 0; t < TOT; ++t) {
        const bool fut = (t >= T);
        float xv[BT], hn[BT];
        unsigned long long Ai[BT], Af[BT], Ag[BT], Ao[BT];

        if (l1) {
            if (!fut) {
                const float* xp = input + (size_t)t * Btot + bglob0 + b0;
                float4 x0 = *(const float4*)(xp);
                float4 x1 = *(const float4*)(xp + 4);
                xv[0] = x0.x; xv[1] = x0.y; xv[2] = x0.z; xv[3] = x0.w;
                xv[4] = x1.x; xv[5] = x1.y; xv[6] = x1.z; xv[7] = x1.w;
            }
            // ---- GEMV on h[t-1]; x not needed yet ----
            #pragma unroll
            for (int bb = 0; bb < BT; bb++) { Ai[bb] = 0ull; Af[bb] = 0ull; Ag[bb] = 0ull; Ao[bb] = 0ull; }

            #pragma unroll 5
            for (int j2 = 0; j2 < NJ2; j2++) {
                ulonglong2 wIF = *(const ulonglong2*)(wp + j2 * 8);      // (wi),(wf)
                ulonglong2 wGO = *(const ulonglong2*)(wp + j2 * 8 + 4);  // (wg),(wo)
                ulonglong2 h01 = *(const ulonglong2*)(hp + j2 * HSTRIDE);       // b0,b0+1
                ulonglong2 h23 = *(const ulonglong2*)(hp + j2 * HSTRIDE + 4);   // b0+2,b0+3
                ulonglong2 h45 = *(const ulonglong2*)(hp + j2 * HSTRIDE + 8);   // b0+4,b0+5
                ulonglong2 h67 = *(const ulonglong2*)(hp + j2 * HSTRIDE + 12);  // b0+6,b0+7
                FMA2(Ai[0], wIF.x, h01.x); FMA2(Af[0], wIF.y, h01.x);
                FMA2(Ag[0], wGO.x, h01.x); FMA2(Ao[0], wGO.y, h01.x);
                FMA2(Ai[1], wIF.x, h01.y); FMA2(Af[1], wIF.y, h01.y);
                FMA2(Ag[1], wGO.x, h01.y); FMA2(Ao[1], wGO.y, h01.y);
                FMA2(Ai[2], wIF.x, h23.x); FMA2(Af[2], wIF.y, h23.x);
                FMA2(Ag[2], wGO.x, h23.x); FMA2(Ao[2], wGO.y, h23.x);
                FMA2(Ai[3], wIF.x, h23.y); FMA2(Af[3], wIF.y, h23.y);
                FMA2(Ag[3], wGO.x, h23.y); FMA2(Ao[3], wGO.y, h23.y);
                FMA2(Ai[4], wIF.x, h45.x); FMA2(Af[4], wIF.y, h45.x);
                FMA2(Ag[4], wGO.x, h45.x); FMA2(Ao[4], wGO.y, h45.x);
                FMA2(Ai[5], wIF.x, h45.y); FMA2(Af[5], wIF.y, h45.y);
                FMA2(Ag[5], wGO.x, h45.y); FMA2(Ao[5], wGO.y, h45.y);
                FMA2(Ai[6], wIF.x, h67.x); FMA2(Af[6], wIF.y, h67.x);
                FMA2(Ag[6], wGO.x, h67.x); FMA2(Ao[6], wGO.y, h67.x);
                FMA2(Ai[7], wIF.x, h67.y); FMA2(Af[7], wIF.y, h67.y);
                FMA2(Ag[7], wGO.x, h67.y); FMA2(Ao[7], wGO.y, h67.y);
            }
        } else if (l2 && t > 0) {
            // ---- layer-2 for step t-1 (concurrent with layer-1's GEMV) ----
            const int tt = t - 1;
            const float* cp = c1sh + bl2;
            float di = 0.f, df = 0.f, dg = 0.f, dz = 0.f;
            #pragma unroll 10
            for (int uu = 0; uu < CELL; uu++) {
                float cv  = cp[uu * CSTRIDE];
                float4 w4 = *(const float4*)(w2i + uu * 4);
                di = fmaf(cv, w4.x, di);
                df = fmaf(cv, w4.y, df);
                dg = fmaf(cv, w4.z, dg);
                dz = fmaf(cv, w4.w, dz);
            }
            float pi = fmaf(h2, whh2[0], di + b2c[0]);
            float pf = fmaf(h2, whh2[1], df + b2c[1]);
            float pg = fmaf(h2, whh2[2], dg + b2c[2]);
            float po = fmaf(h2, whh2[3], dz + b2c[3]);
            float c  = sigm(pf) * c2 + sigm(pi) * tanh_f(pg);
            c2 = c;
            h2 = sigm(po) * tanh_f(c);
            c2sh[bl2] = c;
            if (tt >= T) out[(size_t)(bglob0 + bl2) * FUT + (tt - T)] = c;
        }

        __syncthreads();   // GEMV/c1 reads done; c2sh holds c2[t-1]

        if (l1) {
            if (fut) {
                float4 x0 = *(const float4*)(c2sh + b0);
                float4 x1 = *(const float4*)(c2sh + b0 + 4);
                xv[0] = x0.x; xv[1] = x0.y; xv[2] = x0.z; xv[3] = x0.w;
                xv[4] = x1.x; xv[5] = x1.y; xv[6] = x1.z; xv[7] = x1.w;
            }
            #pragma unroll
            for (int bb = 0; bb < BT; bb++) {
                float e, o;
                UNPK2(e, o, Ai[bb]); float gi = e + o;
                UNPK2(e, o, Af[bb]); float gf = e + o;
                UNPK2(e, o, Ag[bb]); float gg = e + o;
                UNPK2(e, o, Ao[bb]); float go = e + o;
                float pi = fmaf(xv[bb], wih[0], gi + bsum[0]);
                float pf = fmaf(xv[bb], wih[1], gf + bsum[1]);
                float pg = fmaf(xv[bb], wih[2], gg + bsum[2]);
                float po = fmaf(xv[bb], wih[3], go + bsum[3]);
                float c  = sigm(pf) * c1r[bb] + sigm(pi) * tanh_f(pg);
                c1r[bb] = c;
                hn[bb]  = sigm(po) * tanh_f(c);
            }
            #pragma unroll
            for (int bb = 0; bb < BT; bb++) hw[2 * bb] = hn[bb];
            *(float4*)(c1sh + u * CSTRIDE + b0)     = make_float4(c1r[0], c1r[1], c1r[2], c1r[3]);
            *(float4*)(c1sh + u * CSTRIDE + b0 + 4) = make_float4(c1r[4], c1r[5], c1r[6], c1r[7]);
        }

        __syncthreads();   // new h/c1/c2 visible for next step
    }

    // drain: layer-2 for the final step TOT-1
    if (l2) {
        const int tt = TOT - 1;
        const float* cp = c1sh + bl2;
        float di = 0.f, df = 0.f, dg = 0.f, dz = 0.f;
        #pragma unroll 10
        for (int uu = 0; uu < CELL; uu++) {
            float cv  = cp[uu * CSTRIDE];
            float4 w4 = *(const float4*)(w2i + uu * 4);
            di = fmaf(cv, w4.x, di);
            df = fmaf(cv, w4.y, df);
            dg = fmaf(cv, w4.z, dg);
            dz = fmaf(cv, w4.w, dz);
        }
        float pi = fmaf(h2, whh2[0], di + b2c[0]);
        float pf = fmaf(h2, whh2[1], df + b2c[1]);
        float pg = fmaf(h2, whh2[2], dg + b2c[2]);
        float po = fmaf(h2, whh2[3], dz + b2c[3]);
        float c  = sigm(pf) * c2 + sigm(pi) * tanh_f(pg);
        out[(size_t)(bglob0 + bl2) * FUT + (tt - T)] = c;
    }
}

extern "C" void kernel_launch(void* const* d_in, const int* in_sizes, int n_in,
                              void* d_out, int out_size)
{
    const float* input = (const float*)d_in[0];
    const float* W_ih1 = (const float*)d_in[1];
    const float* W_hh1 = (const float*)d_in[2];
    const float* b_ih1 = (const float*)d_in[3];
    const float* b_hh1 = (const float*)d_in[4];
    const float* W_ih2 = (const float*)d_in[5];
    const float* W_hh2 = (const float*)d_in[6];
    const float* b_ih2 = (const float*)d_in[7];
    const float* b_hh2 = (const float*)d_in[8];
    float* out = (float*)d_out;

    const int Btot = 4096;
    const int T    = in_sizes[0] / Btot;   // 512
    const int FUT  = out_size   / Btot;    // 64

    const int smem = (CELL * WSTRIDE     // Wint      40400
                      + NJ2 * HSTRIDE    // hpair      3800
                      + CELL * CSTRIDE   // c1sh       3600
                      + 4 * CELL         // w2i         400
                      + NB)              // c2sh         32
                     * (int)sizeof(float);  // = 192,928 B

    cudaFuncSetAttribute(tsrnn_kernel,
                         cudaFuncAttributeMaxDynamicSharedMemorySize, smem);

    tsrnn_kernel<<<Btot / NB, THREADS, smem>>>(
        input, W_ih1, W_hh1, b_ih1, b_hh1,
        W_ih2, W_hh2, b_ih2, b_hh2,
        out, T, FUT, Btot);
}

// round 8
// speedup vs baseline: 1.9096x; 1.9096x over previous
#include <cuda_runtime.h>
#include <cuda_bf16.h>
#include <cstddef>
#include <cstdint>

// Two-layer LSTM recurrence, persistent kernel, TENSOR-CORE layer-1 GEMV.
// Per block per step: D[32 x 400] = h[32 x 100] @ W_hh1^T, done with
// mma.sync.m16n8k16 bf16 in split precision (W = Whi + Wlo, h = hhi + hlo;
// D = Whi*hhi + Whi*hlo + Wlo*hhi  -> ~fp32 accuracy, fp32 accumulate).
// Gate-interleaved N layout (col = 4u + gate) so a 2-shuffle exchange gives
// each thread all 4 gates of one (batch,unit); that thread owns c1 in regs.
//
// 128 blocks x 352 threads:
//   warps 0-9 : compute. warp w owns n-tiles 5w..5w+4 (units 10w..10w+9),
//               both m-tiles (batch rows 0-31).
//   warp 10   : layer-2 (lane = batch elem), one step behind; also stages x.

#define CELL     100
#define NB       32
#define THREADS  352
#define L2BASE   320
#define KPAD     112      // K padded to 7 k-tiles of 16
#define NKT      21       // 3 passes x 7 k-tiles
#define ASTRIDE  232      // bf16 per A row (hi 0-111, pad, lo 120-231); 464B, quad step 5
#define ALO      120      // col offset of h_lo region (16B aligned)
#define WSTR     120      // bf16 per W row; 240B, quad step 7
#define CSTRIDE  33       // c1sh row stride (floats)

#define LDSM_X4(r0,r1,r2,r3, addr) \
  asm volatile("ldmatrix.sync.aligned.m8n8.x4.shared.b16 {%0,%1,%2,%3}, [%4];" \
    : "=r"(r0), "=r"(r1), "=r"(r2), "=r"(r3) : "r"(addr))
#define LDSM_X2(r0,r1, addr) \
  asm volatile("ldmatrix.sync.aligned.m8n8.x2.shared.b16 {%0,%1}, [%2];" \
    : "=r"(r0), "=r"(r1) : "r"(addr))
#define MMA16816(d, a0,a1,a2,a3, b0,b1) \
  asm volatile("mma.sync.aligned.m16n8k16.row.col.f32.bf16.bf16.f32 " \
    "{%0,%1,%2,%3}, {%4,%5,%6,%7}, {%8,%9}, {%0,%1,%2,%3};" \
    : "+f"((d)[0]), "+f"((d)[1]), "+f"((d)[2]), "+f"((d)[3]) \
    : "r"(a0), "r"(a1), "r"(a2), "r"(a3), "r"(b0), "r"(b1))

__device__ __forceinline__ float sigm(float x) {
    return 1.0f / (1.0f + __expf(-x));
}
__device__ __forceinline__ float tanh_f(float x) {
    float e = __expf(2.0f * x);
    return 1.0f - 2.0f / (e + 1.0f);
}
__device__ __forceinline__ uint32_t smem_u32(const void* p) {
    return (uint32_t)__cvta_generic_to_shared(p);
}

__global__ void __launch_bounds__(THREADS, 1)
tsrnn_kernel(const float* __restrict__ input,
             const float* __restrict__ W_ih1, const float* __restrict__ W_hh1,
             const float* __restrict__ b_ih1, const float* __restrict__ b_hh1,
             const float* __restrict__ W_ih2, const float* __restrict__ W_hh2,
             const float* __restrict__ b_ih2, const float* __restrict__ b_hh2,
             float* __restrict__ out, int T, int FUT, int Btot)
{
    extern __shared__ char smem[];
    __nv_bfloat16* Whi = (__nv_bfloat16*)smem;          // [400][120] row n = 4u+k
    __nv_bfloat16* Wlo = Whi + 400 * WSTR;              // [400][120]
    __nv_bfloat16* Ash = Wlo + 400 * WSTR;              // [32][232]: hhi | pad | hlo
    float* c1sh   = (float*)(Ash + 32 * ASTRIDE);       // [100][33]
    float* w2i    = c1sh + CELL * CSTRIDE;              // [100][4]
    float* wih_sh = w2i + 400;                          // [100][4]
    float* bsum_sh= wih_sh + 400;                       // [100][4]
    float* xsh    = bsum_sh + 400;                      // [32]

    const int tid    = threadIdx.x;
    const int bglob0 = blockIdx.x * NB;
    const int wid    = tid >> 5;
    const int lane   = tid & 31;

    // ================= staging =================
    for (int idx = tid; idx < 400 * KPAD; idx += THREADS) {
        int n = idx / KPAD, kk = idx - n * KPAD;
        int u = n >> 2, k = n & 3;
        float w = (kk < CELL) ? W_hh1[(k * CELL + u) * CELL + kk] : 0.0f;
        __nv_bfloat16 hi = __float2bfloat16(w);
        Whi[n * WSTR + kk] = hi;
        Wlo[n * WSTR + kk] = __float2bfloat16(w - __bfloat162float(hi));
    }
    for (int idx = tid; idx < 32 * ASTRIDE; idx += THREADS)
        Ash[idx] = __float2bfloat16(0.0f);
    for (int idx = tid; idx < CELL * CSTRIDE; idx += THREADS) c1sh[idx] = 0.0f;
    for (int idx = tid; idx < 400; idx += THREADS) {
        int u = idx >> 2, k = idx & 3;
        w2i[idx]    = W_ih2[k * CELL + u];
        wih_sh[idx] = W_ih1[k * CELL + u];
        bsum_sh[idx]= b_ih1[k * CELL + u] + b_hh1[k * CELL + u];
    }
    if (tid < NB) xsh[tid] = 0.0f;

    // ================= per-thread setup =================
    const bool cw = (wid < 10);                 // compute warp
    const bool l2 = (tid >= L2BASE) && (tid < L2BASE + NB);
    const int  q  = lane & 3;
    const int  pp = q & 1;                      // 0: holds (i,f); 1: holds (g,o)
    const int  rowbase = lane >> 2;

    // ldmatrix lane addresses (byte offsets precomputed)
    const uint32_t Au32  = smem_u32(Ash);
    const uint32_t Whi32 = smem_u32(Whi);
    const uint32_t WLO_OFF = (uint32_t)(400 * WSTR * 2); // Wlo - Whi in bytes
    uint32_t aaddr[2], baddr[5];
    if (cw) {
        #pragma unroll
        for (int mt = 0; mt < 2; mt++)
            aaddr[mt] = Au32 + ((mt * 16 + (lane & 15)) * ASTRIDE + (lane >> 4) * 8) * 2;
        const int l4 = lane & 15;
        #pragma unroll
        for (int i = 0; i < 5; i++) {
            int nt = 5 * wid + i;
            baddr[i] = Whi32 + ((8 * nt + (l4 & 7)) * WSTR + ((l4 >> 3) & 1) * 8) * 2;
        }
    }

    // layer-2 per-lane constants + state
    const int bl2 = tid - L2BASE;
    float whh2[4], b2c[4];
    float h2 = 0.0f, c2 = 0.0f;
    if (l2) {
        #pragma unroll
        for (int k = 0; k < 4; k++) {
            whh2[k] = W_hh2[k];
            b2c[k]  = b_ih2[k] + b_hh2[k];
        }
    }

    float c1r[10];
    #pragma unroll
    for (int i = 0; i < 10; i++) c1r[i] = 0.0f;

    __syncthreads();

    // ================= main loop =================
    const int TOT = T + FUT;
    for (int t = 0; t < TOT; ++t) {
        float d[2][5][4];

        if (cw) {
            // ---- phase 1: GEMM on h[t-1] (split bf16, 21 k-tiles) ----
            #pragma unroll
            for (int mt = 0; mt < 2; mt++)
                #pragma unroll
                for (int i = 0; i < 5; i++)
                    #pragma unroll
                    for (int r = 0; r < 4; r++) d[mt][i][r] = 0.0f;

            #pragma unroll
            for (int kt = 0; kt < NKT; kt++) {
                const int p  = kt / 7;            // 0: hi*Whi, 1: lo*Whi, 2: hi*Wlo
                const int kk = kt - p * 7;
                const uint32_t acolb = (uint32_t)((kk * 16 + (p == 1 ? ALO : 0)) * 2);
                const uint32_t bcolb = (uint32_t)(kk * 32) + (p == 2 ? WLO_OFF : 0u);

                uint32_t a0[4], a1[4];
                LDSM_X4(a0[0], a0[1], a0[2], a0[3], aaddr[0] + acolb);
                LDSM_X4(a1[0], a1[1], a1[2], a1[3], aaddr[1] + acolb);
                #pragma unroll
                for (int i = 0; i < 5; i++) {
                    uint32_t b0, b1;
                    LDSM_X2(b0, b1, baddr[i] + bcolb);
                    MMA16816(d[0][i], a0[0], a0[1], a0[2], a0[3], b0, b1);
                    MMA16816(d[1][i], a1[0], a1[1], a1[2], a1[3], b0, b1);
                }
            }
        } else if (l2) {
            // ---- layer-2 for step t-1, and x staging for step t ----
            if (t < T) {
                xsh[bl2] = input[(size_t)t * Btot + bglob0 + bl2];
            }
            if (t > 0) {
                const int tt = t - 1;
                const float* cp = c1sh + bl2;
                float di = 0.f, df = 0.f, dg = 0.f, dz = 0.f;
                #pragma unroll 10
                for (int uu = 0; uu < CELL; uu++) {
                    float cv  = cp[uu * CSTRIDE];
                    float4 w4 = *(const float4*)(w2i + uu * 4);
                    di = fmaf(cv, w4.x, di);
                    df = fmaf(cv, w4.y, df);
                    dg = fmaf(cv, w4.z, dg);
                    dz = fmaf(cv, w4.w, dz);
                }
                float pi = fmaf(h2, whh2[0], di + b2c[0]);
                float pf = fmaf(h2, whh2[1], df + b2c[1]);
                float pg = fmaf(h2, whh2[2], dg + b2c[2]);
                float po = fmaf(h2, whh2[3], dz + b2c[3]);
                float c  = sigm(pf) * c2 + sigm(pi) * tanh_f(pg);
                c2 = c;
                h2 = sigm(po) * tanh_f(c);
                if (t >= T) xsh[bl2] = c;               // x for future step t
                if (tt >= T) out[(size_t)(bglob0 + bl2) * FUT + (tt - T)] = c;
            }
        }

        __syncthreads();   // D ready (regs); A/c1 reads done; xsh holds x(t)

        if (cw) {
            // ---- phase 2: epilogue (gates -> cell -> h split -> stores) ----
            #pragma unroll
            for (int mt = 0; mt < 2; mt++) {
                #pragma unroll
                for (int i = 0; i < 5; i++) {
                    const int u = 2 * (5 * wid + i) + (q >> 1);
                    float* dd = d[mt][i];
                    // exchange with lane^1: even keeps row r, odd keeps row r+8
                    float g0 = pp ? dd[0] : dd[2];
                    float g1 = pp ? dd[1] : dd[3];
                    float r0 = __shfl_xor_sync(0xffffffffu, g0, 1);
                    float r1 = __shfl_xor_sync(0xffffffffu, g1, 1);
                    float gi, gf, gg, go;
                    if (!pp) { gi = dd[0]; gf = dd[1]; gg = r0;    go = r1;    }
                    else     { gi = r0;    gf = r1;    gg = dd[2]; go = dd[3]; }

                    const int row = mt * 16 + rowbase + (pp ? 8 : 0);
                    const float xv = xsh[row];
                    const float4 bs = *(const float4*)(bsum_sh + u * 4);
                    const float4 wi = *(const float4*)(wih_sh + u * 4);
                    float pi = fmaf(xv, wi.x, gi + bs.x);
                    float pf = fmaf(xv, wi.y, gf + bs.y);
                    float pg = fmaf(xv, wi.z, gg + bs.z);
                    float po = fmaf(xv, wi.w, go + bs.w);
                    const int ci = mt * 5 + i;
                    float c = sigm(pf) * c1r[ci] + sigm(pi) * tanh_f(pg);
                    c1r[ci] = c;
                    float h = sigm(po) * tanh_f(c);

                    c1sh[u * CSTRIDE + row] = c;
                    __nv_bfloat16 hh = __float2bfloat16(h);
                    Ash[row * ASTRIDE + u]       = hh;
                    Ash[row * ASTRIDE + ALO + u] =
                        __float2bfloat16(h - __bfloat162float(hh));
                }
            }
        }

        __syncthreads();   // new A / c1 visible for next step
    }

    // drain: layer-2 for the final step TOT-1
    if (l2) {
        const int tt = TOT - 1;
        const float* cp = c1sh + bl2;
        float di = 0.f, df = 0.f, dg = 0.f, dz = 0.f;
        #pragma unroll 10
        for (int uu = 0; uu < CELL; uu++) {
            float cv  = cp[uu * CSTRIDE];
            float4 w4 = *(const float4*)(w2i + uu * 4);
            di = fmaf(cv, w4.x, di);
            df = fmaf(cv, w4.y, df);
            dg = fmaf(cv, w4.z, dg);
            dz = fmaf(cv, w4.w, dz);
        }
        float pi = fmaf(h2, whh2[0], di + b2c[0]);
        float pf = fmaf(h2, whh2[1], df + b2c[1]);
        float pg = fmaf(h2, whh2[2], dg + b2c[2]);
        float po = fmaf(h2, whh2[3], dz + b2c[3]);
        float c  = sigm(pf) * c2 + sigm(pi) * tanh_f(pg);
        out[(size_t)(bglob0 + bl2) * FUT + (tt - T)] = c;
    }
}

extern "C" void kernel_launch(void* const* d_in, const int* in_sizes, int n_in,
                              void* d_out, int out_size)
{
    const float* input = (const float*)d_in[0];
    const float* W_ih1 = (const float*)d_in[1];
    const float* W_hh1 = (const float*)d_in[2];
    const float* b_ih1 = (const float*)d_in[3];
    const float* b_hh1 = (const float*)d_in[4];
    const float* W_ih2 = (const float*)d_in[5];
    const float* W_hh2 = (const float*)d_in[6];
    const float* b_ih2 = (const float*)d_in[7];
    const float* b_hh2 = (const float*)d_in[8];
    float* out = (float*)d_out;

    const int Btot = 4096;
    const int T    = in_sizes[0] / Btot;   // 512
    const int FUT  = out_size   / Btot;    // 64

    const int smem = 400 * WSTR * 2 * 2      // Whi + Wlo      192,000 B
                   + 32 * ASTRIDE * 2        // Ash             14,848 B
                   + (CELL * CSTRIDE         // c1sh             3,300 f
                      + 400 + 400 + 400      // w2i, wih, bsum   1,200 f
                      + NB) * 4;             // xsh                 32 f
                                             // total ~224,976 B

    cudaFuncSetAttribute(tsrnn_kernel,
                         cudaFuncAttributeMaxDynamicSharedMemorySize, smem);

    tsrnn_kernel<<<Btot / NB, THREADS, smem>>>(
        input, W_ih1, W_hh1, b_ih1, b_hh1,
        W_ih2, W_hh2, b_ih2, b_hh2,
        out, T, FUT, Btot);
}